// round 3
// baseline (speedup 1.0000x reference)
#include <cuda_runtime.h>
#include <math.h>

#define NN   50000
#define EE   800000
#define NCLS 21

// ---------------- scratch (device globals: allocation-free) ----------------
__device__ float    g_bufA[(size_t)NN * 256];   // h (W-transformed features)
__device__ float    g_bufB[(size_t)NN * 256];   // aggregated layer output
__device__ float    g_h3[NN * 2];
__device__ float    g_g3[NN * 2];
__device__ float    g_asrc[NN];
__device__ float    g_adst[NN];
__device__ unsigned g_m[NN];
__device__ float    g_denom[NN];
__device__ float    g_e[EE];
__device__ float    g_ex[EE];
__device__ float    g_logits[(size_t)NN * NCLS];
__device__ float    g_cmax[NCLS];
__device__ float    g_clse[NCLS];

// monotone order-preserving float<->uint transform (for atomicMax on floats)
__device__ __forceinline__ unsigned ford(float f) {
    unsigned u = __float_as_uint(f);
    return (u & 0x80000000u) ? ~u : (u | 0x80000000u);
}
__device__ __forceinline__ float finv(unsigned u) {
    return (u & 0x80000000u) ? __uint_as_float(u ^ 0x80000000u)
                             : __uint_as_float(~u);
}

// ---------------- init: out[n,F] = b[F];  m = ord_min ; denom = 0 ----------
__global__ void init_layer_k(float* __restrict__ out, const float* __restrict__ b,
                             unsigned* __restrict__ m, float* __restrict__ denom,
                             int F, int n) {
    int i = blockIdx.x * blockDim.x + threadIdx.x;
    int total = n * F;
    if (i < total) out[i] = b[i % F];
    if (i < n) { m[i] = 0u; denom[i] = 0.f; }
}

// ---------------- GEMM (one node per block) + fused attention dots ---------
template<int FIN, int FOUT, bool RELU_IN>
__global__ void __launch_bounds__(FOUT) gemm_att_k(
    const float* __restrict__ X, const float* __restrict__ W,
    const float* __restrict__ avs, const float* __restrict__ avd,
    float* __restrict__ H, float* __restrict__ asrc, float* __restrict__ adst,
    int n)
{
    __shared__ float xs[FIN];
    __shared__ float rs[FOUT];
    __shared__ float rd[FOUT];
    int node = blockIdx.x;
    if (node >= n) return;
    int j = threadIdx.x;
    for (int k = j; k < FIN; k += FOUT) {
        float v = X[(size_t)node * FIN + k];
        if (RELU_IN) v = fmaxf(v, 0.f);
        xs[k] = v;
    }
    __syncthreads();
    float acc = 0.f;
#pragma unroll 8
    for (int k = 0; k < FIN; ++k)
        acc = fmaf(xs[k], W[k * FOUT + j], acc);
    H[(size_t)node * FOUT + j] = acc;
    rs[j] = acc * avs[j];
    rd[j] = acc * avd[j];
    __syncthreads();
    for (int off = FOUT >> 1; off > 0; off >>= 1) {
        if (j < off) { rs[j] += rs[j + off]; rd[j] += rd[j + off]; }
        __syncthreads();
    }
    if (j == 0) { asrc[node] = rs[0]; adst[node] = rd[0]; }
}

// ---------------- layer-3 GEMM (Fin=256 -> Fout=2) -------------------------
__global__ void __launch_bounds__(256) gemm3_k(
    const float* __restrict__ X, const float* __restrict__ W,
    const float* __restrict__ avs, const float* __restrict__ avd,
    float* __restrict__ H3, float* __restrict__ asrc, float* __restrict__ adst,
    int n)
{
    __shared__ float s0[256], s1[256];
    int node = blockIdx.x;
    if (node >= n) return;
    int t = threadIdx.x;
    float x = X[(size_t)node * 256 + t];
    s0[t] = x * W[t * 2 + 0];
    s1[t] = x * W[t * 2 + 1];
    __syncthreads();
    for (int off = 128; off > 0; off >>= 1) {
        if (t < off) { s0[t] += s0[t + off]; s1[t] += s1[t + off]; }
        __syncthreads();
    }
    if (t == 0) {
        float h0 = s0[0], h1 = s1[0];
        H3[node * 2 + 0] = h0;
        H3[node * 2 + 1] = h1;
        asrc[node] = h0 * avs[0] + h1 * avs[1];
        adst[node] = h0 * avd[0] + h1 * avd[1];
    }
}

// ---------------- edge attention logits + segment max -----------------------
__global__ void edge_logits_k(const int* __restrict__ ei,
                              const float* __restrict__ asrc,
                              const float* __restrict__ adst,
                              float* __restrict__ eo, unsigned* __restrict__ m,
                              int E)
{
    int e = blockIdx.x * blockDim.x + threadIdx.x;
    if (e >= E) return;
    int s = ei[e];
    int d = ei[E + e];
    float v = asrc[s] + adst[d];
    v = (v >= 0.f) ? v : 0.2f * v;   // leaky_relu, slope 0.2
    eo[e] = v;
    atomicMax(&m[d], ford(v));
}

// ---------------- exp(e - m[dst]) + segment sum ------------------------------
__global__ void edge_exp_k(const int* __restrict__ ei,
                           const float* __restrict__ ein,
                           const unsigned* __restrict__ m,
                           float* __restrict__ exo, float* __restrict__ denom,
                           int E)
{
    int e = blockIdx.x * blockDim.x + threadIdx.x;
    if (e >= E) return;
    int d = ei[E + e];
    float v = expf(ein[e] - finv(m[d]));
    exo[e] = v;
    atomicAdd(&denom[d], v);
}

// ---------------- weighted aggregation (warp per edge) ----------------------
template<int F>
__global__ void aggregate_k(const int* __restrict__ ei,
                            const float* __restrict__ H,
                            const float* __restrict__ ex,
                            const float* __restrict__ denom,
                            float* __restrict__ out, int E)
{
    int gw = (blockIdx.x * blockDim.x + threadIdx.x) >> 5;
    int lane = threadIdx.x & 31;
    if (gw >= E) return;
    int s = ei[gw];
    int d = ei[E + gw];
    float alpha = ex[gw] / (denom[d] + 1e-16f);
#pragma unroll
    for (int f = lane; f < F; f += 32)
        atomicAdd(&out[(size_t)d * F + f], alpha * H[(size_t)s * F + f]);
}

__global__ void aggregate2_k(const int* __restrict__ ei,
                             const float* __restrict__ H,
                             const float* __restrict__ ex,
                             const float* __restrict__ denom,
                             float* __restrict__ out, int E)
{
    int e = blockIdx.x * blockDim.x + threadIdx.x;
    if (e >= E) return;
    int s = ei[e];
    int d = ei[E + e];
    float alpha = ex[e] / (denom[d] + 1e-16f);
    atomicAdd(&out[d * 2 + 0], alpha * H[s * 2 + 0]);
    atomicAdd(&out[d * 2 + 1], alpha * H[s * 2 + 1]);
}

// ---------------- classifier: logits = g3 @ Wc + bc --------------------------
__global__ void classifier_k(const float* __restrict__ G3,
                             const float* __restrict__ Wc,
                             const float* __restrict__ bc,
                             float* __restrict__ logits, int n)
{
    int i = blockIdx.x * blockDim.x + threadIdx.x;
    if (i >= n) return;
    float g0 = G3[2 * i], g1 = G3[2 * i + 1];
#pragma unroll
    for (int c = 0; c < NCLS; ++c)
        logits[(size_t)i * NCLS + c] =
            fmaf(g0, Wc[c], fmaf(g1, Wc[NCLS + c], bc[c]));
}

// ---------------- log_softmax over axis 0 (per class column) -----------------
__global__ void col_max_k(const float* __restrict__ logits,
                          float* __restrict__ cmax, int n)
{
    __shared__ float sm[256];
    int c = blockIdx.x;
    float m = -INFINITY;
    for (int i = threadIdx.x; i < n; i += 256)
        m = fmaxf(m, logits[(size_t)i * NCLS + c]);
    sm[threadIdx.x] = m;
    __syncthreads();
    for (int off = 128; off > 0; off >>= 1) {
        if (threadIdx.x < off)
            sm[threadIdx.x] = fmaxf(sm[threadIdx.x], sm[threadIdx.x + off]);
        __syncthreads();
    }
    if (threadIdx.x == 0) cmax[c] = sm[0];
}

__global__ void col_lse_k(const float* __restrict__ logits,
                          const float* __restrict__ cmax,
                          float* __restrict__ clse, int n)
{
    __shared__ float sm[256];
    int c = blockIdx.x;
    float m = cmax[c];
    float s = 0.f;
    for (int i = threadIdx.x; i < n; i += 256)
        s += expf(logits[(size_t)i * NCLS + c] - m);
    sm[threadIdx.x] = s;
    __syncthreads();
    for (int off = 128; off > 0; off >>= 1) {
        if (threadIdx.x < off) sm[threadIdx.x] += sm[threadIdx.x + off];
        __syncthreads();
    }
    if (threadIdx.x == 0) clse[c] = logf(sm[0]);
}

__global__ void final_k(const float* __restrict__ logits,
                        const float* __restrict__ cmax,
                        const float* __restrict__ clse,
                        float* __restrict__ out, int total)
{
    int i = blockIdx.x * blockDim.x + threadIdx.x;
    if (i >= total) return;
    int c = i % NCLS;
    out[i] = logits[i] - cmax[c] - clse[c];
}

// ---------------- launch ------------------------------------------------------
extern "C" void kernel_launch(void* const* d_in, const int* in_sizes, int n_in,
                              void* d_out, int out_size)
{
    const float* x   = (const float*)d_in[0];
    const int*   ei  = (const int*)d_in[1];   // int32 [2, E] (JAX x64 disabled)
    // d_in[2] = edge_attr (unused by reference)
    const float* W1  = (const float*)d_in[3];
    const float* a1s = (const float*)d_in[4];
    const float* a1d = (const float*)d_in[5];
    const float* b1  = (const float*)d_in[6];
    const float* W2  = (const float*)d_in[7];
    const float* a2s = (const float*)d_in[8];
    const float* a2d = (const float*)d_in[9];
    const float* b2  = (const float*)d_in[10];
    const float* W3  = (const float*)d_in[11];
    const float* a3s = (const float*)d_in[12];
    const float* a3d = (const float*)d_in[13];
    const float* b3  = (const float*)d_in[14];
    const float* Wc  = (const float*)d_in[15];
    const float* bc  = (const float*)d_in[16];

    int n = in_sizes[0] / 256;
    int E = in_sizes[1] / 2;
    if (n > NN) n = NN;
    if (E > EE) E = EE;

    float *bufA, *bufB, *h3, *g3, *asrc, *adst, *denom, *ebuf, *exbuf;
    float *logits, *cmax, *clse;
    unsigned* m;
    cudaGetSymbolAddress((void**)&bufA,   g_bufA);
    cudaGetSymbolAddress((void**)&bufB,   g_bufB);
    cudaGetSymbolAddress((void**)&h3,     g_h3);
    cudaGetSymbolAddress((void**)&g3,     g_g3);
    cudaGetSymbolAddress((void**)&asrc,   g_asrc);
    cudaGetSymbolAddress((void**)&adst,   g_adst);
    cudaGetSymbolAddress((void**)&m,      g_m);
    cudaGetSymbolAddress((void**)&denom,  g_denom);
    cudaGetSymbolAddress((void**)&ebuf,   g_e);
    cudaGetSymbolAddress((void**)&exbuf,  g_ex);
    cudaGetSymbolAddress((void**)&logits, g_logits);
    cudaGetSymbolAddress((void**)&cmax,   g_cmax);
    cudaGetSymbolAddress((void**)&clse,   g_clse);

    float* out = (float*)d_out;

    const int TB = 256;
    int eb  = (E + TB - 1) / TB;              // per-edge kernels
    int ewb = (E * 32 + TB - 1) / TB;         // warp-per-edge kernels

    // ================= layer 1: x[256] -> 64 =================
    init_layer_k<<<(n * 64 + TB - 1) / TB, TB>>>(bufB, b1, m, denom, 64, n);
    gemm_att_k<256, 64, false><<<n, 64>>>(x, W1, a1s, a1d, bufA, asrc, adst, n);
    edge_logits_k<<<eb, TB>>>(ei, asrc, adst, ebuf, m, E);
    edge_exp_k<<<eb, TB>>>(ei, ebuf, m, exbuf, denom, E);
    aggregate_k<64><<<ewb, TB>>>(ei, bufA, exbuf, denom, bufB, E);
    // bufB = GAT1 out + b1   (ReLU fused into next GEMM's input load)

    // ================= layer 2: 64 -> 256 =================
    gemm_att_k<64, 256, true><<<n, 256>>>(bufB, W2, a2s, a2d, bufA, asrc, adst, n);
    init_layer_k<<<(n * 256 + TB - 1) / TB, TB>>>(bufB, b2, m, denom, 256, n);
    edge_logits_k<<<eb, TB>>>(ei, asrc, adst, ebuf, m, E);
    edge_exp_k<<<eb, TB>>>(ei, ebuf, m, exbuf, denom, E);
    aggregate_k<256><<<ewb, TB>>>(ei, bufA, exbuf, denom, bufB, E);

    // ================= layer 3: 256 -> 2 =================
    gemm3_k<<<n, 256>>>(bufB, W3, a3s, a3d, h3, asrc, adst, n);
    init_layer_k<<<(n * 2 + TB - 1) / TB, TB>>>(g3, b3, m, denom, 2, n);
    edge_logits_k<<<eb, TB>>>(ei, asrc, adst, ebuf, m, E);
    edge_exp_k<<<eb, TB>>>(ei, ebuf, m, exbuf, denom, E);
    aggregate2_k<<<eb, TB>>>(ei, h3, exbuf, denom, g3, E);

    // ================= classifier + log_softmax(axis=0) =================
    classifier_k<<<(n + TB - 1) / TB, TB>>>(g3, Wc, bc, logits, n);
    col_max_k<<<NCLS, 256>>>(logits, cmax, n);
    col_lse_k<<<NCLS, 256>>>(logits, cmax, clse, n);
    final_k<<<(n * NCLS + TB - 1) / TB, TB>>>(logits, cmax, clse, out, n * NCLS);
}

// round 4
// speedup vs baseline: 1.4472x; 1.4472x over previous
#include <cuda_runtime.h>
#include <math.h>

#define NN   50000
#define EE   800000
#define NCLS 21

// ---------------- scratch (device globals: allocation-free) ----------------
__device__ float g_bufA[(size_t)NN * 256];   // h (W-transformed features)
__device__ float g_bufB[(size_t)NN * 256];   // aggregated layer output
__device__ float g_h3[NN * 2];
__device__ float g_g3[NN * 2];
__device__ float g_asrc[NN];
__device__ float g_adst[NN];
__device__ int   g_deg[NN];
__device__ int   g_incl[NN];
__device__ int   g_rowptr[NN + 1];
__device__ int   g_pos[NN];
__device__ int   g_col[EE];
__device__ int   g_bsum[256];
__device__ float g_logits[(size_t)NN * NCLS];
__device__ float g_cmax[NCLS];
__device__ float g_clse[NCLS];

// =================== CSR build (dst-sorted) ===================
__global__ void zero_deg_k(int* __restrict__ deg, int n) {
    int i = blockIdx.x * blockDim.x + threadIdx.x;
    if (i < n) deg[i] = 0;
}

__global__ void hist_k(const int* __restrict__ ei, int* __restrict__ deg, int E) {
    int e = blockIdx.x * blockDim.x + threadIdx.x;
    if (e < E) atomicAdd(&deg[ei[E + e]], 1);
}

__global__ void scan1_k(const int* __restrict__ deg, int* __restrict__ incl,
                        int* __restrict__ bsum, int n) {
    __shared__ int s[256];
    int t = threadIdx.x;
    int gid = blockIdx.x * 256 + t;
    int v = (gid < n) ? deg[gid] : 0;
    s[t] = v;
    __syncthreads();
    for (int off = 1; off < 256; off <<= 1) {
        int u = (t >= off) ? s[t - off] : 0;
        __syncthreads();
        s[t] += u;
        __syncthreads();
    }
    if (gid < n) incl[gid] = s[t];
    if (t == 255) bsum[blockIdx.x] = s[255];
}

__global__ void scan2_k(int* __restrict__ bsum, int nb) {
    __shared__ int s[256];
    int t = threadIdx.x;
    int v = (t < nb) ? bsum[t] : 0;
    s[t] = v;
    __syncthreads();
    for (int off = 1; off < 256; off <<= 1) {
        int u = (t >= off) ? s[t - off] : 0;
        __syncthreads();
        s[t] += u;
        __syncthreads();
    }
    if (t < nb) bsum[t] = s[t] - v;   // exclusive
}

__global__ void scan3_k(const int* __restrict__ incl, const int* __restrict__ deg,
                        const int* __restrict__ bsum, int* __restrict__ rowptr,
                        int* __restrict__ pos, int n) {
    int gid = blockIdx.x * 256 + threadIdx.x;
    if (gid < n) {
        int v = incl[gid] + bsum[blockIdx.x];
        rowptr[gid + 1] = v;
        pos[gid] = v - deg[gid];
    }
    if (gid == 0) rowptr[0] = 0;
}

__global__ void scatter_k(const int* __restrict__ ei, int* __restrict__ pos,
                          int* __restrict__ col, int E) {
    int e = blockIdx.x * blockDim.x + threadIdx.x;
    if (e >= E) return;
    int s = ei[e];
    int d = ei[E + e];
    int p = atomicAdd(&pos[d], 1);
    col[p] = s;
}

// =================== tiled GEMM: H = (relu?)X @ W ===================
template<int FIN, int FOUT, int NPB, bool RELU_IN>
__global__ void __launch_bounds__(FOUT) gemm_k(
    const float* __restrict__ X, const float* __restrict__ W,
    float* __restrict__ H, int n)
{
    __shared__ __align__(16) float xs[NPB][FIN];
    int node0 = blockIdx.x * NPB;
    int j = threadIdx.x;
    for (int idx = j; idx < NPB * FIN; idx += FOUT) {
        int m = idx / FIN, k = idx % FIN;
        int node = node0 + m;
        float v = (node < n) ? X[(size_t)node * FIN + k] : 0.f;
        if (RELU_IN) v = fmaxf(v, 0.f);
        xs[m][k] = v;
    }
    __syncthreads();
    float acc[NPB];
#pragma unroll
    for (int m = 0; m < NPB; m++) acc[m] = 0.f;
    for (int k = 0; k < FIN; k += 4) {
        float w0 = W[(k + 0) * FOUT + j];
        float w1 = W[(k + 1) * FOUT + j];
        float w2 = W[(k + 2) * FOUT + j];
        float w3 = W[(k + 3) * FOUT + j];
#pragma unroll
        for (int m = 0; m < NPB; m++) {
            float4 xv = *(const float4*)&xs[m][k];
            acc[m] = fmaf(xv.x, w0, acc[m]);
            acc[m] = fmaf(xv.y, w1, acc[m]);
            acc[m] = fmaf(xv.z, w2, acc[m]);
            acc[m] = fmaf(xv.w, w3, acc[m]);
        }
    }
#pragma unroll
    for (int m = 0; m < NPB; m++) {
        int node = node0 + m;
        if (node < n) H[(size_t)node * FOUT + j] = acc[m];
    }
}

// =================== attention dots: asrc = h·a_s, adst = h·a_d ===================
template<int F>
__global__ void __launch_bounds__(F) att_dots_k(
    const float* __restrict__ H, const float* __restrict__ avs,
    const float* __restrict__ avd, float* __restrict__ asrc,
    float* __restrict__ adst, int n)
{
    __shared__ float rs[F], rd[F];
    int node = blockIdx.x;
    if (node >= n) return;
    int t = threadIdx.x;
    float h = H[(size_t)node * F + t];
    rs[t] = h * avs[t];
    rd[t] = h * avd[t];
    __syncthreads();
    for (int off = F / 2; off > 0; off >>= 1) {
        if (t < off) { rs[t] += rs[t + off]; rd[t] += rd[t + off]; }
        __syncthreads();
    }
    if (t == 0) { asrc[node] = rs[0]; adst[node] = rd[0]; }
}

// =================== fused segment-softmax + aggregation (block per dst) =====
template<int F>
__global__ void __launch_bounds__(F) gat_agg_k(
    const int* __restrict__ rowptr, const int* __restrict__ col,
    const float* __restrict__ H, const float* __restrict__ asrc,
    const float* __restrict__ adst, const float* __restrict__ bias,
    float* __restrict__ out, int n)
{
    __shared__ float red[F];
    __shared__ float sex[F];
    __shared__ int   ssrc[F];
    __shared__ float m_sh;
    int d = blockIdx.x;
    if (d >= n) return;
    int tid = threadIdx.x;
    int r0 = rowptr[d], r1 = rowptr[d + 1];
    if (r0 == r1) { out[(size_t)d * F + tid] = bias[tid]; return; }
    float ad = adst[d];

    // pass 1: segment max of leaky logits
    float mloc = -INFINITY;
    for (int j = r0 + tid; j < r1; j += F) {
        float e = asrc[col[j]] + ad;
        e = (e >= 0.f) ? e : 0.2f * e;
        mloc = fmaxf(mloc, e);
    }
    red[tid] = mloc;
    __syncthreads();
    for (int off = F / 2; off > 0; off >>= 1) {
        if (tid < off) red[tid] = fmaxf(red[tid], red[tid + off]);
        __syncthreads();
    }
    if (tid == 0) m_sh = red[0];
    __syncthreads();
    float m = m_sh;

    // pass 2: acc = sum exp(e-m) * h[src], sloc = sum exp(e-m)
    float acc = 0.f, sloc = 0.f;
    for (int chunk = r0; chunk < r1; chunk += F) {
        int j = chunk + tid;
        if (j < r1) {
            int s = col[j];
            float e = asrc[s] + ad;
            e = (e >= 0.f) ? e : 0.2f * e;
            float ex = expf(e - m);
            sex[tid] = ex;
            ssrc[tid] = s;
            sloc += ex;
        }
        __syncthreads();
        int cnt = min(F, r1 - chunk);
        int k = 0;
        float a0 = 0.f, a1 = 0.f, a2 = 0.f, a3 = 0.f;
        for (; k + 4 <= cnt; k += 4) {
            a0 = fmaf(sex[k + 0], H[(size_t)ssrc[k + 0] * F + tid], a0);
            a1 = fmaf(sex[k + 1], H[(size_t)ssrc[k + 1] * F + tid], a1);
            a2 = fmaf(sex[k + 2], H[(size_t)ssrc[k + 2] * F + tid], a2);
            a3 = fmaf(sex[k + 3], H[(size_t)ssrc[k + 3] * F + tid], a3);
        }
        for (; k < cnt; k++)
            a0 = fmaf(sex[k], H[(size_t)ssrc[k] * F + tid], a0);
        acc += (a0 + a1) + (a2 + a3);
        __syncthreads();
    }

    red[tid] = sloc;
    __syncthreads();
    for (int off = F / 2; off > 0; off >>= 1) {
        if (tid < off) red[tid] += red[tid + off];
        __syncthreads();
    }
    float den = red[0];
    out[(size_t)d * F + tid] = acc / (den + 1e-16f) + bias[tid];
}

// =================== layer-3 GEMM (256 -> 2), warp per node ===================
__global__ void gemm3_k(const float* __restrict__ X, const float* __restrict__ W,
                        const float* __restrict__ avs, const float* __restrict__ avd,
                        float* __restrict__ H3, float* __restrict__ asrc,
                        float* __restrict__ adst, int n)
{
    int warp = (blockIdx.x * blockDim.x + threadIdx.x) >> 5;
    int lane = threadIdx.x & 31;
    if (warp >= n) return;
    const float* xr = X + (size_t)warp * 256;
    float a0 = 0.f, a1 = 0.f;
#pragma unroll
    for (int i = 0; i < 8; i++) {
        int k = lane + 32 * i;
        float x = xr[k];
        a0 = fmaf(x, W[2 * k + 0], a0);
        a1 = fmaf(x, W[2 * k + 1], a1);
    }
#pragma unroll
    for (int off = 16; off > 0; off >>= 1) {
        a0 += __shfl_xor_sync(0xffffffffu, a0, off);
        a1 += __shfl_xor_sync(0xffffffffu, a1, off);
    }
    if (lane == 0) {
        H3[warp * 2 + 0] = a0;
        H3[warp * 2 + 1] = a1;
        asrc[warp] = a0 * avs[0] + a1 * avs[1];
        adst[warp] = a0 * avd[0] + a1 * avd[1];
    }
}

// =================== layer-3 fused agg (warp per dst, F=2) ===================
__global__ void gat_agg2_k(const int* __restrict__ rowptr, const int* __restrict__ col,
                           const float* __restrict__ H, const float* __restrict__ asrc,
                           const float* __restrict__ adst, const float* __restrict__ bias,
                           float* __restrict__ out, int n)
{
    int d = (blockIdx.x * blockDim.x + threadIdx.x) >> 5;
    int lane = threadIdx.x & 31;
    if (d >= n) return;
    int r0 = rowptr[d], r1 = rowptr[d + 1];
    if (r0 == r1) {
        if (lane < 2) out[d * 2 + lane] = bias[lane];
        return;
    }
    float ad = adst[d];
    float m = -INFINITY;
    for (int j = r0 + lane; j < r1; j += 32) {
        float e = asrc[col[j]] + ad;
        e = (e >= 0.f) ? e : 0.2f * e;
        m = fmaxf(m, e);
    }
#pragma unroll
    for (int off = 16; off > 0; off >>= 1)
        m = fmaxf(m, __shfl_xor_sync(0xffffffffu, m, off));

    float s = 0.f, h0 = 0.f, h1 = 0.f;
    for (int j = r0 + lane; j < r1; j += 32) {
        int src = col[j];
        float e = asrc[src] + ad;
        e = (e >= 0.f) ? e : 0.2f * e;
        float ex = expf(e - m);
        s += ex;
        h0 = fmaf(ex, H[src * 2 + 0], h0);
        h1 = fmaf(ex, H[src * 2 + 1], h1);
    }
#pragma unroll
    for (int off = 16; off > 0; off >>= 1) {
        s  += __shfl_xor_sync(0xffffffffu, s,  off);
        h0 += __shfl_xor_sync(0xffffffffu, h0, off);
        h1 += __shfl_xor_sync(0xffffffffu, h1, off);
    }
    if (lane == 0) {
        float inv = 1.f / (s + 1e-16f);
        out[d * 2 + 0] = h0 * inv + bias[0];
        out[d * 2 + 1] = h1 * inv + bias[1];
    }
}

// =================== classifier + log_softmax(axis=0) ===================
__global__ void classifier_k(const float* __restrict__ G3,
                             const float* __restrict__ Wc,
                             const float* __restrict__ bc,
                             float* __restrict__ logits, int n)
{
    int i = blockIdx.x * blockDim.x + threadIdx.x;
    if (i >= n) return;
    float g0 = G3[2 * i], g1 = G3[2 * i + 1];
#pragma unroll
    for (int c = 0; c < NCLS; ++c)
        logits[(size_t)i * NCLS + c] =
            fmaf(g0, Wc[c], fmaf(g1, Wc[NCLS + c], bc[c]));
}

__global__ void col_max_k(const float* __restrict__ logits,
                          float* __restrict__ cmax, int n)
{
    __shared__ float sm[256];
    int c = blockIdx.x;
    float m = -INFINITY;
    for (int i = threadIdx.x; i < n; i += 256)
        m = fmaxf(m, logits[(size_t)i * NCLS + c]);
    sm[threadIdx.x] = m;
    __syncthreads();
    for (int off = 128; off > 0; off >>= 1) {
        if (threadIdx.x < off)
            sm[threadIdx.x] = fmaxf(sm[threadIdx.x], sm[threadIdx.x + off]);
        __syncthreads();
    }
    if (threadIdx.x == 0) cmax[c] = sm[0];
}

__global__ void col_lse_k(const float* __restrict__ logits,
                          const float* __restrict__ cmax,
                          float* __restrict__ clse, int n)
{
    __shared__ float sm[256];
    int c = blockIdx.x;
    float m = cmax[c];
    float s = 0.f;
    for (int i = threadIdx.x; i < n; i += 256)
        s += expf(logits[(size_t)i * NCLS + c] - m);
    sm[threadIdx.x] = s;
    __syncthreads();
    for (int off = 128; off > 0; off >>= 1) {
        if (threadIdx.x < off) sm[threadIdx.x] += sm[threadIdx.x + off];
        __syncthreads();
    }
    if (threadIdx.x == 0) clse[c] = logf(sm[0]);
}

__global__ void final_k(const float* __restrict__ logits,
                        const float* __restrict__ cmax,
                        const float* __restrict__ clse,
                        float* __restrict__ out, int total)
{
    int i = blockIdx.x * blockDim.x + threadIdx.x;
    if (i >= total) return;
    int c = i % NCLS;
    out[i] = logits[i] - cmax[c] - clse[c];
}

// =================== launch ===================
extern "C" void kernel_launch(void* const* d_in, const int* in_sizes, int n_in,
                              void* d_out, int out_size)
{
    const float* x   = (const float*)d_in[0];
    const int*   ei  = (const int*)d_in[1];   // int32 [2, E]
    const float* W1  = (const float*)d_in[3];
    const float* a1s = (const float*)d_in[4];
    const float* a1d = (const float*)d_in[5];
    const float* b1  = (const float*)d_in[6];
    const float* W2  = (const float*)d_in[7];
    const float* a2s = (const float*)d_in[8];
    const float* a2d = (const float*)d_in[9];
    const float* b2  = (const float*)d_in[10];
    const float* W3  = (const float*)d_in[11];
    const float* a3s = (const float*)d_in[12];
    const float* a3d = (const float*)d_in[13];
    const float* b3  = (const float*)d_in[14];
    const float* Wc  = (const float*)d_in[15];
    const float* bc  = (const float*)d_in[16];

    int n = in_sizes[0] / 256;
    int E = in_sizes[1] / 2;
    if (n > NN) n = NN;
    if (E > EE) E = EE;

    float *bufA, *bufB, *h3, *g3, *asrc, *adst, *logits, *cmax, *clse;
    int *deg, *incl, *rowptr, *pos, *colx, *bsum;
    cudaGetSymbolAddress((void**)&bufA,   g_bufA);
    cudaGetSymbolAddress((void**)&bufB,   g_bufB);
    cudaGetSymbolAddress((void**)&h3,     g_h3);
    cudaGetSymbolAddress((void**)&g3,     g_g3);
    cudaGetSymbolAddress((void**)&asrc,   g_asrc);
    cudaGetSymbolAddress((void**)&adst,   g_adst);
    cudaGetSymbolAddress((void**)&deg,    g_deg);
    cudaGetSymbolAddress((void**)&incl,   g_incl);
    cudaGetSymbolAddress((void**)&rowptr, g_rowptr);
    cudaGetSymbolAddress((void**)&pos,    g_pos);
    cudaGetSymbolAddress((void**)&colx,   g_col);
    cudaGetSymbolAddress((void**)&bsum,   g_bsum);
    cudaGetSymbolAddress((void**)&logits, g_logits);
    cudaGetSymbolAddress((void**)&cmax,   g_cmax);
    cudaGetSymbolAddress((void**)&clse,   g_clse);

    float* out = (float*)d_out;

    const int TB = 256;
    int nb = (n + TB - 1) / TB;          // node blocks (also scan blocks)
    int eb = (E + TB - 1) / TB;          // edge blocks
    int gb = (n + 7) / 8;                // gemm blocks (8 nodes each)
    int wb = (n * 32 + TB - 1) / TB;     // warp-per-node blocks

    // ---- CSR build (dst-sorted), reused by all 3 layers ----
    zero_deg_k<<<nb, TB>>>(deg, n);
    hist_k<<<eb, TB>>>(ei, deg, E);
    scan1_k<<<nb, TB>>>(deg, incl, bsum, n);
    scan2_k<<<1, TB>>>(bsum, nb);
    scan3_k<<<nb, TB>>>(incl, deg, bsum, rowptr, pos, n);
    scatter_k<<<eb, TB>>>(ei, pos, colx, E);

    // ---- layer 1: 256 -> 64 ----
    gemm_k<256, 64, 8, false><<<gb, 64>>>(x, W1, bufA, n);
    att_dots_k<64><<<n, 64>>>(bufA, a1s, a1d, asrc, adst, n);
    gat_agg_k<64><<<n, 64>>>(rowptr, colx, bufA, asrc, adst, b1, bufB, n);

    // ---- layer 2: 64 -> 256 (ReLU fused into input load) ----
    gemm_k<64, 256, 8, true><<<gb, 256>>>(bufB, W2, bufA, n);
    att_dots_k<256><<<n, 256>>>(bufA, a2s, a2d, asrc, adst, n);
    gat_agg_k<256><<<n, 256>>>(rowptr, colx, bufA, asrc, adst, b2, bufB, n);

    // ---- layer 3: 256 -> 2 ----
    gemm3_k<<<wb, TB>>>(bufB, W3, a3s, a3d, h3, asrc, adst, n);
    gat_agg2_k<<<wb, TB>>>(rowptr, colx, h3, asrc, adst, b3, g3, n);

    // ---- classifier + log_softmax over nodes ----
    classifier_k<<<(n + TB - 1) / TB, TB>>>(g3, Wc, bc, logits, n);
    col_max_k<<<NCLS, 256>>>(logits, cmax, n);
    col_lse_k<<<NCLS, 256>>>(logits, cmax, clse, n);
    final_k<<<(n * NCLS + TB - 1) / TB, TB>>>(logits, cmax, clse, out, n * NCLS);
}

// round 5
// speedup vs baseline: 2.1869x; 1.5111x over previous
#include <cuda_runtime.h>
#include <math.h>

#define NN   50000
#define EE   800000
#define NCLS 21

// ---------------- scratch (device globals: allocation-free) ----------------
__device__ float g_bufA[(size_t)NN * 256];   // h (W-transformed features)
__device__ float g_bufB[(size_t)NN * 256];   // aggregated layer output
__device__ float g_h3[NN * 2];
__device__ float g_g3[NN * 2];
__device__ float g_asrc[NN];
__device__ float g_adst[NN];
__device__ int   g_deg[NN];
__device__ int   g_incl[NN];
__device__ int   g_rowptr[NN + 1];
__device__ int   g_pos[NN];
__device__ int   g_col[EE];
__device__ int   g_bsum[256];
__device__ float g_logits[(size_t)NN * NCLS];
__device__ float g_cmax[NCLS];
__device__ float g_clse[NCLS];

// =================== CSR build (dst-sorted) ===================
__global__ void zero_deg_k(int* __restrict__ deg, int n) {
    int i = blockIdx.x * blockDim.x + threadIdx.x;
    if (i < n) deg[i] = 0;
}

__global__ void hist_k(const int* __restrict__ ei, int* __restrict__ deg, int E) {
    int e = blockIdx.x * blockDim.x + threadIdx.x;
    if (e < E) atomicAdd(&deg[ei[E + e]], 1);
}

__global__ void scan1_k(const int* __restrict__ deg, int* __restrict__ incl,
                        int* __restrict__ bsum, int n) {
    __shared__ int s[256];
    int t = threadIdx.x;
    int gid = blockIdx.x * 256 + t;
    int v = (gid < n) ? deg[gid] : 0;
    s[t] = v;
    __syncthreads();
    for (int off = 1; off < 256; off <<= 1) {
        int u = (t >= off) ? s[t - off] : 0;
        __syncthreads();
        s[t] += u;
        __syncthreads();
    }
    if (gid < n) incl[gid] = s[t];
    if (t == 255) bsum[blockIdx.x] = s[255];
}

__global__ void scan2_k(int* __restrict__ bsum, int nb) {
    __shared__ int s[256];
    int t = threadIdx.x;
    int v = (t < nb) ? bsum[t] : 0;
    s[t] = v;
    __syncthreads();
    for (int off = 1; off < 256; off <<= 1) {
        int u = (t >= off) ? s[t - off] : 0;
        __syncthreads();
        s[t] += u;
        __syncthreads();
    }
    if (t < nb) bsum[t] = s[t] - v;   // exclusive
}

__global__ void scan3_k(const int* __restrict__ incl, const int* __restrict__ deg,
                        const int* __restrict__ bsum, int* __restrict__ rowptr,
                        int* __restrict__ pos, int n) {
    int gid = blockIdx.x * 256 + threadIdx.x;
    if (gid < n) {
        int v = incl[gid] + bsum[blockIdx.x];
        rowptr[gid + 1] = v;
        pos[gid] = v - deg[gid];
    }
    if (gid == 0) rowptr[0] = 0;
}

__global__ void scatter_k(const int* __restrict__ ei, int* __restrict__ pos,
                          int* __restrict__ col, int E) {
    int e = blockIdx.x * blockDim.x + threadIdx.x;
    if (e >= E) return;
    int s = ei[e];
    int d = ei[E + e];
    int p = atomicAdd(&pos[d], 1);
    col[p] = s;
}

// ====== tiled GEMM: H = (relu?)X @ W, fused attention dots into epilogue ======
template<int FIN, int FOUT, int NPB, bool RELU_IN>
__global__ void __launch_bounds__(FOUT) gemm_att_k(
    const float* __restrict__ X, const float* __restrict__ W,
    const float* __restrict__ avs, const float* __restrict__ avd,
    float* __restrict__ H, float* __restrict__ asrc, float* __restrict__ adst,
    int n)
{
    constexpr int NW = FOUT / 32;
    __shared__ __align__(16) float xs[NPB][FIN];
    __shared__ float sp[NPB][NW], sd[NPB][NW];
    int node0 = blockIdx.x * NPB;
    int j = threadIdx.x;
    int w = j >> 5, lane = j & 31;
    for (int idx = j; idx < NPB * FIN; idx += FOUT) {
        int m = idx / FIN, k = idx % FIN;
        int node = node0 + m;
        float v = (node < n) ? X[(size_t)node * FIN + k] : 0.f;
        if (RELU_IN) v = fmaxf(v, 0.f);
        xs[m][k] = v;
    }
    __syncthreads();
    float acc[NPB];
#pragma unroll
    for (int m = 0; m < NPB; m++) acc[m] = 0.f;
    for (int k = 0; k < FIN; k += 4) {
        float w0 = W[(k + 0) * FOUT + j];
        float w1 = W[(k + 1) * FOUT + j];
        float w2 = W[(k + 2) * FOUT + j];
        float w3 = W[(k + 3) * FOUT + j];
#pragma unroll
        for (int m = 0; m < NPB; m++) {
            float4 xv = *(const float4*)&xs[m][k];
            acc[m] = fmaf(xv.x, w0, acc[m]);
            acc[m] = fmaf(xv.y, w1, acc[m]);
            acc[m] = fmaf(xv.z, w2, acc[m]);
            acc[m] = fmaf(xv.w, w3, acc[m]);
        }
    }
    float avsj = avs[j], avdj = avd[j];
#pragma unroll
    for (int m = 0; m < NPB; m++) {
        int node = node0 + m;
        if (node < n) H[(size_t)node * FOUT + j] = acc[m];
        float ps = acc[m] * avsj;
        float pd = acc[m] * avdj;
#pragma unroll
        for (int off = 16; off > 0; off >>= 1) {
            ps += __shfl_xor_sync(0xffffffffu, ps, off);
            pd += __shfl_xor_sync(0xffffffffu, pd, off);
        }
        if (lane == 0) { sp[m][w] = ps; sd[m][w] = pd; }
    }
    __syncthreads();
    if (j < NPB) {
        int node = node0 + j;
        if (node < n) {
            float s = 0.f;
#pragma unroll
            for (int ww = 0; ww < NW; ww++) s += sp[j][ww];
            asrc[node] = s;
        }
    } else if (j < 2 * NPB) {
        int m = j - NPB;
        int node = node0 + m;
        if (node < n) {
            float s = 0.f;
#pragma unroll
            for (int ww = 0; ww < NW; ww++) s += sd[m][ww];
            adst[node] = s;
        }
    }
}

// ====== fused segment-softmax + aggregation: warp per dst, vector gathers =====
// F floats per row; each lane owns VPL = F/32 consecutive floats.
template<int F>
__global__ void __launch_bounds__(256) gat_agg_w(
    const int* __restrict__ rowptr, const int* __restrict__ col,
    const float* __restrict__ H, const float* __restrict__ asrc,
    const float* __restrict__ adst, const float* __restrict__ bias,
    float* __restrict__ out, int n)
{
    constexpr int VPL = F / 32;          // 2 for F=64, 8 for F=256
    constexpr int NV4 = VPL / 4;         // float4 count (0 if VPL<4)
    int d = (blockIdx.x * blockDim.x + threadIdx.x) >> 5;
    int lane = threadIdx.x & 31;
    if (d >= n) return;
    int r0 = rowptr[d], r1 = rowptr[d + 1];
    int base = lane * VPL;
    if (r0 == r1) {
#pragma unroll
        for (int i = 0; i < VPL; i++)
            out[(size_t)d * F + base + i] = bias[base + i];
        return;
    }
    float ad = adst[d];

    // pass 1: segment max of leaky-relu logits
    float m = -INFINITY;
    for (int j = r0 + lane; j < r1; j += 32) {
        float e = asrc[col[j]] + ad;
        e = (e >= 0.f) ? e : 0.2f * e;
        m = fmaxf(m, e);
    }
#pragma unroll
    for (int off = 16; off > 0; off >>= 1)
        m = fmaxf(m, __shfl_xor_sync(0xffffffffu, m, off));

    // pass 2: acc = sum ex * h[src, base..], ssum = sum ex
    float acc[VPL];
#pragma unroll
    for (int i = 0; i < VPL; i++) acc[i] = 0.f;
    float ssum = 0.f;
    for (int chunk = r0; chunk < r1; chunk += 32) {
        int j = chunk + lane;
        float ex = 0.f;
        int s = 0;
        if (j < r1) {
            s = col[j];
            float e = asrc[s] + ad;          // L1-hot from pass 1
            e = (e >= 0.f) ? e : 0.2f * e;
            ex = expf(e - m);
            ssum += ex;
        }
        int cnt = min(32, r1 - chunk);
        for (int k = 0; k < cnt; k++) {
            float exk = __shfl_sync(0xffffffffu, ex, k);
            int sk = __shfl_sync(0xffffffffu, s, k);
            const float* row = &H[(size_t)sk * F + base];
            if (NV4 > 0) {
#pragma unroll
                for (int v = 0; v < (NV4 > 0 ? NV4 : 1); v++) {
                    float4 hv = *(const float4*)&row[v * 4];
                    acc[v * 4 + 0] = fmaf(exk, hv.x, acc[v * 4 + 0]);
                    acc[v * 4 + 1] = fmaf(exk, hv.y, acc[v * 4 + 1]);
                    acc[v * 4 + 2] = fmaf(exk, hv.z, acc[v * 4 + 2]);
                    acc[v * 4 + 3] = fmaf(exk, hv.w, acc[v * 4 + 3]);
                }
            } else {
                float2 hv = *(const float2*)&row[0];
                acc[0] = fmaf(exk, hv.x, acc[0]);
                acc[1] = fmaf(exk, hv.y, acc[1]);
            }
        }
    }
#pragma unroll
    for (int off = 16; off > 0; off >>= 1)
        ssum += __shfl_xor_sync(0xffffffffu, ssum, off);
    float inv = 1.f / (ssum + 1e-16f);
#pragma unroll
    for (int i = 0; i < VPL; i++)
        out[(size_t)d * F + base + i] = acc[i] * inv + bias[base + i];
}

// =================== layer-3 GEMM (256 -> 2), warp per node ===================
__global__ void gemm3_k(const float* __restrict__ X, const float* __restrict__ W,
                        const float* __restrict__ avs, const float* __restrict__ avd,
                        float* __restrict__ H3, float* __restrict__ asrc,
                        float* __restrict__ adst, int n)
{
    int warp = (blockIdx.x * blockDim.x + threadIdx.x) >> 5;
    int lane = threadIdx.x & 31;
    if (warp >= n) return;
    const float* xr = X + (size_t)warp * 256;
    float a0 = 0.f, a1 = 0.f;
#pragma unroll
    for (int i = 0; i < 8; i++) {
        int k = lane + 32 * i;
        float x = xr[k];
        a0 = fmaf(x, W[2 * k + 0], a0);
        a1 = fmaf(x, W[2 * k + 1], a1);
    }
#pragma unroll
    for (int off = 16; off > 0; off >>= 1) {
        a0 += __shfl_xor_sync(0xffffffffu, a0, off);
        a1 += __shfl_xor_sync(0xffffffffu, a1, off);
    }
    if (lane == 0) {
        H3[warp * 2 + 0] = a0;
        H3[warp * 2 + 1] = a1;
        asrc[warp] = a0 * avs[0] + a1 * avs[1];
        adst[warp] = a0 * avd[0] + a1 * avd[1];
    }
}

// =================== layer-3 fused agg (warp per dst, F=2) ===================
__global__ void gat_agg2_k(const int* __restrict__ rowptr, const int* __restrict__ col,
                           const float* __restrict__ H, const float* __restrict__ asrc,
                           const float* __restrict__ adst, const float* __restrict__ bias,
                           float* __restrict__ out, int n)
{
    int d = (blockIdx.x * blockDim.x + threadIdx.x) >> 5;
    int lane = threadIdx.x & 31;
    if (d >= n) return;
    int r0 = rowptr[d], r1 = rowptr[d + 1];
    if (r0 == r1) {
        if (lane < 2) out[d * 2 + lane] = bias[lane];
        return;
    }
    float ad = adst[d];
    float m = -INFINITY;
    for (int j = r0 + lane; j < r1; j += 32) {
        float e = asrc[col[j]] + ad;
        e = (e >= 0.f) ? e : 0.2f * e;
        m = fmaxf(m, e);
    }
#pragma unroll
    for (int off = 16; off > 0; off >>= 1)
        m = fmaxf(m, __shfl_xor_sync(0xffffffffu, m, off));

    float s = 0.f, h0 = 0.f, h1 = 0.f;
    for (int j = r0 + lane; j < r1; j += 32) {
        int src = col[j];
        float e = asrc[src] + ad;
        e = (e >= 0.f) ? e : 0.2f * e;
        float ex = expf(e - m);
        s += ex;
        float2 hv = *(const float2*)&H[src * 2];
        h0 = fmaf(ex, hv.x, h0);
        h1 = fmaf(ex, hv.y, h1);
    }
#pragma unroll
    for (int off = 16; off > 0; off >>= 1) {
        s  += __shfl_xor_sync(0xffffffffu, s,  off);
        h0 += __shfl_xor_sync(0xffffffffu, h0, off);
        h1 += __shfl_xor_sync(0xffffffffu, h1, off);
    }
    if (lane == 0) {
        float inv = 1.f / (s + 1e-16f);
        out[d * 2 + 0] = h0 * inv + bias[0];
        out[d * 2 + 1] = h1 * inv + bias[1];
    }
}

// =================== classifier + log_softmax(axis=0) ===================
__global__ void classifier_k(const float* __restrict__ G3,
                             const float* __restrict__ Wc,
                             const float* __restrict__ bc,
                             float* __restrict__ logits, int n)
{
    int i = blockIdx.x * blockDim.x + threadIdx.x;
    if (i >= n) return;
    float g0 = G3[2 * i], g1 = G3[2 * i + 1];
#pragma unroll
    for (int c = 0; c < NCLS; ++c)
        logits[(size_t)i * NCLS + c] =
            fmaf(g0, Wc[c], fmaf(g1, Wc[NCLS + c], bc[c]));
}

__global__ void col_stats_k(const float* __restrict__ logits,
                            float* __restrict__ cmax, float* __restrict__ clse,
                            int n)
{
    __shared__ float sm[256];
    __shared__ float mshared;
    int c = blockIdx.x;
    int t = threadIdx.x;
    float m = -INFINITY;
    for (int i = t; i < n; i += 256)
        m = fmaxf(m, logits[(size_t)i * NCLS + c]);
    sm[t] = m;
    __syncthreads();
    for (int off = 128; off > 0; off >>= 1) {
        if (t < off) sm[t] = fmaxf(sm[t], sm[t + off]);
        __syncthreads();
    }
    if (t == 0) { mshared = sm[0]; cmax[c] = sm[0]; }
    __syncthreads();
    float mm = mshared;
    float s = 0.f;
    for (int i = t; i < n; i += 256)
        s += expf(logits[(size_t)i * NCLS + c] - mm);
    sm[t] = s;
    __syncthreads();
    for (int off = 128; off > 0; off >>= 1) {
        if (t < off) sm[t] += sm[t + off];
        __syncthreads();
    }
    if (t == 0) clse[c] = logf(sm[0]);
}

__global__ void final_k(const float* __restrict__ logits,
                        const float* __restrict__ cmax,
                        const float* __restrict__ clse,
                        float* __restrict__ out, int total)
{
    int i = blockIdx.x * blockDim.x + threadIdx.x;
    if (i >= total) return;
    int c = i % NCLS;
    out[i] = logits[i] - cmax[c] - clse[c];
}

// =================== launch ===================
extern "C" void kernel_launch(void* const* d_in, const int* in_sizes, int n_in,
                              void* d_out, int out_size)
{
    const float* x   = (const float*)d_in[0];
    const int*   ei  = (const int*)d_in[1];   // int32 [2, E]
    const float* W1  = (const float*)d_in[3];
    const float* a1s = (const float*)d_in[4];
    const float* a1d = (const float*)d_in[5];
    const float* b1  = (const float*)d_in[6];
    const float* W2  = (const float*)d_in[7];
    const float* a2s = (const float*)d_in[8];
    const float* a2d = (const float*)d_in[9];
    const float* b2  = (const float*)d_in[10];
    const float* W3  = (const float*)d_in[11];
    const float* a3s = (const float*)d_in[12];
    const float* a3d = (const float*)d_in[13];
    const float* b3  = (const float*)d_in[14];
    const float* Wc  = (const float*)d_in[15];
    const float* bc  = (const float*)d_in[16];

    int n = in_sizes[0] / 256;
    int E = in_sizes[1] / 2;
    if (n > NN) n = NN;
    if (E > EE) E = EE;

    float *bufA, *bufB, *h3, *g3, *asrc, *adst, *logits, *cmax, *clse;
    int *deg, *incl, *rowptr, *pos, *colx, *bsum;
    cudaGetSymbolAddress((void**)&bufA,   g_bufA);
    cudaGetSymbolAddress((void**)&bufB,   g_bufB);
    cudaGetSymbolAddress((void**)&h3,     g_h3);
    cudaGetSymbolAddress((void**)&g3,     g_g3);
    cudaGetSymbolAddress((void**)&asrc,   g_asrc);
    cudaGetSymbolAddress((void**)&adst,   g_adst);
    cudaGetSymbolAddress((void**)&deg,    g_deg);
    cudaGetSymbolAddress((void**)&incl,   g_incl);
    cudaGetSymbolAddress((void**)&rowptr, g_rowptr);
    cudaGetSymbolAddress((void**)&pos,    g_pos);
    cudaGetSymbolAddress((void**)&colx,   g_col);
    cudaGetSymbolAddress((void**)&bsum,   g_bsum);
    cudaGetSymbolAddress((void**)&logits, g_logits);
    cudaGetSymbolAddress((void**)&cmax,   g_cmax);
    cudaGetSymbolAddress((void**)&clse,   g_clse);

    float* out = (float*)d_out;

    const int TB = 256;
    int nb = (n + TB - 1) / TB;          // node blocks (also scan blocks)
    int eb = (E + TB - 1) / TB;          // edge blocks
    int gb = (n + 7) / 8;                // gemm blocks (8 nodes each)
    int wb = (n * 32 + TB - 1) / TB;     // warp-per-node blocks

    // ---- CSR build (dst-sorted), reused by all 3 layers ----
    zero_deg_k<<<nb, TB>>>(deg, n);
    hist_k<<<eb, TB>>>(ei, deg, E);
    scan1_k<<<nb, TB>>>(deg, incl, bsum, n);
    scan2_k<<<1, TB>>>(bsum, nb);
    scan3_k<<<nb, TB>>>(incl, deg, bsum, rowptr, pos, n);
    scatter_k<<<eb, TB>>>(ei, pos, colx, E);

    // ---- layer 1: 256 -> 64 ----
    gemm_att_k<256, 64, 8, false><<<gb, 64>>>(x, W1, a1s, a1d, bufA, asrc, adst, n);
    gat_agg_w<64><<<wb, TB>>>(rowptr, colx, bufA, asrc, adst, b1, bufB, n);

    // ---- layer 2: 64 -> 256 (ReLU fused into input load) ----
    gemm_att_k<64, 256, 8, true><<<gb, 256>>>(bufB, W2, a2s, a2d, bufA, asrc, adst, n);
    gat_agg_w<256><<<wb, TB>>>(rowptr, colx, bufA, asrc, adst, b2, bufB, n);

    // ---- layer 3: 256 -> 2 ----
    gemm3_k<<<wb, TB>>>(bufB, W3, a3s, a3d, h3, asrc, adst, n);
    gat_agg2_k<<<wb, TB>>>(rowptr, colx, h3, asrc, adst, b3, g3, n);

    // ---- classifier + log_softmax over nodes ----
    classifier_k<<<(n + TB - 1) / TB, TB>>>(g3, Wc, bc, logits, n);
    col_stats_k<<<NCLS, 256>>>(logits, cmax, clse, n);
    final_k<<<(n * NCLS + TB - 1) / TB, TB>>>(logits, cmax, clse, out, n * NCLS);
}

// round 6
// speedup vs baseline: 2.2298x; 1.0196x over previous
#include <cuda_runtime.h>
#include <math.h>

#define NN   50000
#define EE   800000
#define NCLS 21

// ---------------- scratch (device globals: allocation-free) ----------------
__device__ float g_bufA[(size_t)NN * 256];   // h (W-transformed features)
__device__ float g_bufB[(size_t)NN * 256];   // aggregated layer output
__device__ float g_h3[NN * 2];
__device__ float g_g3[NN * 2];
__device__ float g_asrc[NN];
__device__ float g_adst[NN];
__device__ float g_ex[EE];
__device__ float g_dinv[NN];
__device__ int   g_deg[NN];
__device__ int   g_incl[NN];
__device__ int   g_rowptr[NN + 1];
__device__ int   g_pos[NN];
__device__ int   g_col[EE];
__device__ int   g_bsum[256];
__device__ float g_logits[(size_t)NN * NCLS];
__device__ float g_cmax[NCLS];
__device__ float g_clse[NCLS];

// =================== CSR build (dst-sorted) ===================
__global__ void zero_deg_k(int* __restrict__ deg, int n) {
    int i = blockIdx.x * blockDim.x + threadIdx.x;
    if (i < n) deg[i] = 0;
}

__global__ void hist_k(const int* __restrict__ ei, int* __restrict__ deg, int E) {
    int e = blockIdx.x * blockDim.x + threadIdx.x;
    if (e < E) atomicAdd(&deg[ei[E + e]], 1);
}

__global__ void scan1_k(const int* __restrict__ deg, int* __restrict__ incl,
                        int* __restrict__ bsum, int n) {
    __shared__ int s[256];
    int t = threadIdx.x;
    int gid = blockIdx.x * 256 + t;
    int v = (gid < n) ? deg[gid] : 0;
    s[t] = v;
    __syncthreads();
    for (int off = 1; off < 256; off <<= 1) {
        int u = (t >= off) ? s[t - off] : 0;
        __syncthreads();
        s[t] += u;
        __syncthreads();
    }
    if (gid < n) incl[gid] = s[t];
    if (t == 255) bsum[blockIdx.x] = s[255];
}

__global__ void scan2_k(int* __restrict__ bsum, int nb) {
    __shared__ int s[256];
    int t = threadIdx.x;
    int v = (t < nb) ? bsum[t] : 0;
    s[t] = v;
    __syncthreads();
    for (int off = 1; off < 256; off <<= 1) {
        int u = (t >= off) ? s[t - off] : 0;
        __syncthreads();
        s[t] += u;
        __syncthreads();
    }
    if (t < nb) bsum[t] = s[t] - v;   // exclusive
}

__global__ void scan3_k(const int* __restrict__ incl, const int* __restrict__ deg,
                        const int* __restrict__ bsum, int* __restrict__ rowptr,
                        int* __restrict__ pos, int n) {
    int gid = blockIdx.x * 256 + threadIdx.x;
    if (gid < n) {
        int v = incl[gid] + bsum[blockIdx.x];
        rowptr[gid + 1] = v;
        pos[gid] = v - deg[gid];
    }
    if (gid == 0) rowptr[0] = 0;
}

__global__ void scatter_k(const int* __restrict__ ei, int* __restrict__ pos,
                          int* __restrict__ col, int E) {
    int e = blockIdx.x * blockDim.x + threadIdx.x;
    if (e >= E) return;
    int s = ei[e];
    int d = ei[E + e];
    int p = atomicAdd(&pos[d], 1);
    col[p] = s;
}

// ====== tiled GEMM: H = (relu?)X @ W, fused attention dots into epilogue ======
template<int FIN, int FOUT, int NPB, bool RELU_IN>
__global__ void __launch_bounds__(FOUT) gemm_att_k(
    const float* __restrict__ X, const float* __restrict__ W,
    const float* __restrict__ avs, const float* __restrict__ avd,
    float* __restrict__ H, float* __restrict__ asrc, float* __restrict__ adst,
    int n)
{
    constexpr int NW = FOUT / 32;
    __shared__ __align__(16) float xs[NPB][FIN];
    __shared__ float sp[NPB][NW], sd[NPB][NW];
    int node0 = blockIdx.x * NPB;
    int j = threadIdx.x;
    int w = j >> 5, lane = j & 31;
    for (int idx = j; idx < NPB * FIN; idx += FOUT) {
        int m = idx / FIN, k = idx % FIN;
        int node = node0 + m;
        float v = (node < n) ? X[(size_t)node * FIN + k] : 0.f;
        if (RELU_IN) v = fmaxf(v, 0.f);
        xs[m][k] = v;
    }
    __syncthreads();
    float acc[NPB];
#pragma unroll
    for (int m = 0; m < NPB; m++) acc[m] = 0.f;
    for (int k = 0; k < FIN; k += 4) {
        float w0 = W[(k + 0) * FOUT + j];
        float w1 = W[(k + 1) * FOUT + j];
        float w2 = W[(k + 2) * FOUT + j];
        float w3 = W[(k + 3) * FOUT + j];
#pragma unroll
        for (int m = 0; m < NPB; m++) {
            float4 xv = *(const float4*)&xs[m][k];
            acc[m] = fmaf(xv.x, w0, acc[m]);
            acc[m] = fmaf(xv.y, w1, acc[m]);
            acc[m] = fmaf(xv.z, w2, acc[m]);
            acc[m] = fmaf(xv.w, w3, acc[m]);
        }
    }
    float avsj = avs[j], avdj = avd[j];
#pragma unroll
    for (int m = 0; m < NPB; m++) {
        int node = node0 + m;
        if (node < n) H[(size_t)node * FOUT + j] = acc[m];
        float ps = acc[m] * avsj;
        float pd = acc[m] * avdj;
#pragma unroll
        for (int off = 16; off > 0; off >>= 1) {
            ps += __shfl_xor_sync(0xffffffffu, ps, off);
            pd += __shfl_xor_sync(0xffffffffu, pd, off);
        }
        if (lane == 0) { sp[m][w] = ps; sd[m][w] = pd; }
    }
    __syncthreads();
    if (j < NPB) {
        int node = node0 + j;
        if (node < n) {
            float s = 0.f;
#pragma unroll
            for (int ww = 0; ww < NW; ww++) s += sp[j][ww];
            asrc[node] = s;
        }
    } else if (j < 2 * NPB) {
        int m = j - NPB;
        int node = node0 + m;
        if (node < n) {
            float s = 0.f;
#pragma unroll
            for (int ww = 0; ww < NW; ww++) s += sd[m][ww];
            adst[node] = s;
        }
    }
}

// ====== alpha precompute: warp per dst; writes ex[e] and dinv[d] ==============
__global__ void __launch_bounds__(256) alpha_k(
    const int* __restrict__ rowptr, const int* __restrict__ col,
    const float* __restrict__ asrc, const float* __restrict__ adst,
    float* __restrict__ ex, float* __restrict__ dinv, int n)
{
    int d = (blockIdx.x * blockDim.x + threadIdx.x) >> 5;
    int lane = threadIdx.x & 31;
    if (d >= n) return;
    int r0 = rowptr[d], r1 = rowptr[d + 1];
    if (r0 == r1) { if (lane == 0) dinv[d] = 0.f; return; }
    float ad = adst[d];

    float m = -INFINITY;
    for (int j = r0 + lane; j < r1; j += 32) {
        float e = asrc[col[j]] + ad;
        e = (e >= 0.f) ? e : 0.2f * e;
        m = fmaxf(m, e);
    }
#pragma unroll
    for (int off = 16; off > 0; off >>= 1)
        m = fmaxf(m, __shfl_xor_sync(0xffffffffu, m, off));

    float s = 0.f;
    for (int j = r0 + lane; j < r1; j += 32) {
        float e = asrc[col[j]] + ad;
        e = (e >= 0.f) ? e : 0.2f * e;
        float v = expf(e - m);
        ex[j] = v;
        s += v;
    }
#pragma unroll
    for (int off = 16; off > 0; off >>= 1)
        s += __shfl_xor_sync(0xffffffffu, s, off);
    if (lane == 0) dinv[d] = 1.f / (s + 1e-16f);
}

// ====== pure weighted gather aggregation: WPD warps per dst ====================
template<int F, int WPD>
__global__ void __launch_bounds__(256) agg_gather_k(
    const int* __restrict__ rowptr, const int* __restrict__ col,
    const float* __restrict__ H, const float* __restrict__ ex,
    const float* __restrict__ dinv, const float* __restrict__ bias,
    float* __restrict__ out, int n)
{
    constexpr int VPL = F / (32 * WPD);   // floats per lane
    int gw = (blockIdx.x * blockDim.x + threadIdx.x) >> 5;
    int d = gw / WPD;
    int part = gw % WPD;
    int lane = threadIdx.x & 31;
    if (d >= n) return;
    int base = part * (F / WPD) + lane * VPL;
    int r0 = rowptr[d], r1 = rowptr[d + 1];
    if (r0 == r1) {
#pragma unroll
        for (int i = 0; i < VPL; i++)
            out[(size_t)d * F + base + i] = bias[base + i];
        return;
    }
    float acc[VPL];
#pragma unroll
    for (int i = 0; i < VPL; i++) acc[i] = 0.f;

    for (int chunk = r0; chunk < r1; chunk += 32) {
        int j = chunk + lane;
        int s = 0; float exv = 0.f;
        if (j < r1) { s = col[j]; exv = ex[j]; }
        int cnt = min(32, r1 - chunk);
        for (int k = 0; k < cnt; k++) {
            float exk = __shfl_sync(0xffffffffu, exv, k);
            int sk = __shfl_sync(0xffffffffu, s, k);
            const float* row = &H[(size_t)sk * F + base];
            if (VPL == 4) {
                float4 hv = *(const float4*)row;
                acc[0] = fmaf(exk, hv.x, acc[0]);
                acc[1] = fmaf(exk, hv.y, acc[1]);
                acc[2] = fmaf(exk, hv.z, acc[2]);
                acc[3] = fmaf(exk, hv.w, acc[3]);
            } else if (VPL == 2) {
                float2 hv = *(const float2*)row;
                acc[0] = fmaf(exk, hv.x, acc[0]);
                acc[1] = fmaf(exk, hv.y, acc[1]);
            } else {
#pragma unroll
                for (int v = 0; v < VPL; v += 4) {
                    float4 hv = *(const float4*)&row[v];
                    acc[v + 0] = fmaf(exk, hv.x, acc[v + 0]);
                    acc[v + 1] = fmaf(exk, hv.y, acc[v + 1]);
                    acc[v + 2] = fmaf(exk, hv.z, acc[v + 2]);
                    acc[v + 3] = fmaf(exk, hv.w, acc[v + 3]);
                }
            }
        }
    }
    float inv = dinv[d];
#pragma unroll
    for (int i = 0; i < VPL; i++)
        out[(size_t)d * F + base + i] = acc[i] * inv + bias[base + i];
}

// =================== layer-3 GEMM (256 -> 2), warp per node ===================
__global__ void gemm3_k(const float* __restrict__ X, const float* __restrict__ W,
                        const float* __restrict__ avs, const float* __restrict__ avd,
                        float* __restrict__ H3, float* __restrict__ asrc,
                        float* __restrict__ adst, int n)
{
    int warp = (blockIdx.x * blockDim.x + threadIdx.x) >> 5;
    int lane = threadIdx.x & 31;
    if (warp >= n) return;
    const float* xr = X + (size_t)warp * 256;
    float a0 = 0.f, a1 = 0.f;
#pragma unroll
    for (int i = 0; i < 8; i++) {
        int k = lane + 32 * i;
        float x = xr[k];
        a0 = fmaf(x, W[2 * k + 0], a0);
        a1 = fmaf(x, W[2 * k + 1], a1);
    }
#pragma unroll
    for (int off = 16; off > 0; off >>= 1) {
        a0 += __shfl_xor_sync(0xffffffffu, a0, off);
        a1 += __shfl_xor_sync(0xffffffffu, a1, off);
    }
    if (lane == 0) {
        H3[warp * 2 + 0] = a0;
        H3[warp * 2 + 1] = a1;
        asrc[warp] = a0 * avs[0] + a1 * avs[1];
        adst[warp] = a0 * avd[0] + a1 * avd[1];
    }
}

// =================== layer-3 fused agg (warp per dst, F=2) ===================
__global__ void gat_agg2_k(const int* __restrict__ rowptr, const int* __restrict__ col,
                           const float* __restrict__ H, const float* __restrict__ asrc,
                           const float* __restrict__ adst, const float* __restrict__ bias,
                           float* __restrict__ out, int n)
{
    int d = (blockIdx.x * blockDim.x + threadIdx.x) >> 5;
    int lane = threadIdx.x & 31;
    if (d >= n) return;
    int r0 = rowptr[d], r1 = rowptr[d + 1];
    if (r0 == r1) {
        if (lane < 2) out[d * 2 + lane] = bias[lane];
        return;
    }
    float ad = adst[d];
    float m = -INFINITY;
    for (int j = r0 + lane; j < r1; j += 32) {
        float e = asrc[col[j]] + ad;
        e = (e >= 0.f) ? e : 0.2f * e;
        m = fmaxf(m, e);
    }
#pragma unroll
    for (int off = 16; off > 0; off >>= 1)
        m = fmaxf(m, __shfl_xor_sync(0xffffffffu, m, off));

    float s = 0.f, h0 = 0.f, h1 = 0.f;
    for (int j = r0 + lane; j < r1; j += 32) {
        int src = col[j];
        float e = asrc[src] + ad;
        e = (e >= 0.f) ? e : 0.2f * e;
        float exv = expf(e - m);
        s += exv;
        float2 hv = *(const float2*)&H[src * 2];
        h0 = fmaf(exv, hv.x, h0);
        h1 = fmaf(exv, hv.y, h1);
    }
#pragma unroll
    for (int off = 16; off > 0; off >>= 1) {
        s  += __shfl_xor_sync(0xffffffffu, s,  off);
        h0 += __shfl_xor_sync(0xffffffffu, h0, off);
        h1 += __shfl_xor_sync(0xffffffffu, h1, off);
    }
    if (lane == 0) {
        float inv = 1.f / (s + 1e-16f);
        out[d * 2 + 0] = h0 * inv + bias[0];
        out[d * 2 + 1] = h1 * inv + bias[1];
    }
}

// =================== classifier + log_softmax(axis=0) ===================
__global__ void classifier_k(const float* __restrict__ G3,
                             const float* __restrict__ Wc,
                             const float* __restrict__ bc,
                             float* __restrict__ logits, int n)
{
    int i = blockIdx.x * blockDim.x + threadIdx.x;
    if (i >= n) return;
    float g0 = G3[2 * i], g1 = G3[2 * i + 1];
#pragma unroll
    for (int c = 0; c < NCLS; ++c)
        logits[(size_t)i * NCLS + c] =
            fmaf(g0, Wc[c], fmaf(g1, Wc[NCLS + c], bc[c]));
}

__global__ void col_stats_k(const float* __restrict__ logits,
                            float* __restrict__ cmax, float* __restrict__ clse,
                            int n)
{
    __shared__ float sm[256];
    __shared__ float mshared;
    int c = blockIdx.x;
    int t = threadIdx.x;
    float m = -INFINITY;
    for (int i = t; i < n; i += 256)
        m = fmaxf(m, logits[(size_t)i * NCLS + c]);
    sm[t] = m;
    __syncthreads();
    for (int off = 128; off > 0; off >>= 1) {
        if (t < off) sm[t] = fmaxf(sm[t], sm[t + off]);
        __syncthreads();
    }
    if (t == 0) { mshared = sm[0]; cmax[c] = sm[0]; }
    __syncthreads();
    float mm = mshared;
    float s = 0.f;
    for (int i = t; i < n; i += 256)
        s += expf(logits[(size_t)i * NCLS + c] - mm);
    sm[t] = s;
    __syncthreads();
    for (int off = 128; off > 0; off >>= 1) {
        if (t < off) sm[t] += sm[t + off];
        __syncthreads();
    }
    if (t == 0) clse[c] = logf(sm[0]);
}

__global__ void final_k(const float* __restrict__ logits,
                        const float* __restrict__ cmax,
                        const float* __restrict__ clse,
                        float* __restrict__ out, int total)
{
    int i = blockIdx.x * blockDim.x + threadIdx.x;
    if (i >= total) return;
    int c = i % NCLS;
    out[i] = logits[i] - cmax[c] - clse[c];
}

// =================== launch ===================
extern "C" void kernel_launch(void* const* d_in, const int* in_sizes, int n_in,
                              void* d_out, int out_size)
{
    const float* x   = (const float*)d_in[0];
    const int*   ei  = (const int*)d_in[1];   // int32 [2, E]
    const float* W1  = (const float*)d_in[3];
    const float* a1s = (const float*)d_in[4];
    const float* a1d = (const float*)d_in[5];
    const float* b1  = (const float*)d_in[6];
    const float* W2  = (const float*)d_in[7];
    const float* a2s = (const float*)d_in[8];
    const float* a2d = (const float*)d_in[9];
    const float* b2  = (const float*)d_in[10];
    const float* W3  = (const float*)d_in[11];
    const float* a3s = (const float*)d_in[12];
    const float* a3d = (const float*)d_in[13];
    const float* b3  = (const float*)d_in[14];
    const float* Wc  = (const float*)d_in[15];
    const float* bc  = (const float*)d_in[16];

    int n = in_sizes[0] / 256;
    int E = in_sizes[1] / 2;
    if (n > NN) n = NN;
    if (E > EE) E = EE;

    float *bufA, *bufB, *h3, *g3, *asrc, *adst, *exbuf, *dinv;
    float *logits, *cmax, *clse;
    int *deg, *incl, *rowptr, *pos, *colx, *bsum;
    cudaGetSymbolAddress((void**)&bufA,   g_bufA);
    cudaGetSymbolAddress((void**)&bufB,   g_bufB);
    cudaGetSymbolAddress((void**)&h3,     g_h3);
    cudaGetSymbolAddress((void**)&g3,     g_g3);
    cudaGetSymbolAddress((void**)&asrc,   g_asrc);
    cudaGetSymbolAddress((void**)&adst,   g_adst);
    cudaGetSymbolAddress((void**)&exbuf,  g_ex);
    cudaGetSymbolAddress((void**)&dinv,   g_dinv);
    cudaGetSymbolAddress((void**)&deg,    g_deg);
    cudaGetSymbolAddress((void**)&incl,   g_incl);
    cudaGetSymbolAddress((void**)&rowptr, g_rowptr);
    cudaGetSymbolAddress((void**)&pos,    g_pos);
    cudaGetSymbolAddress((void**)&colx,   g_col);
    cudaGetSymbolAddress((void**)&bsum,   g_bsum);
    cudaGetSymbolAddress((void**)&logits, g_logits);
    cudaGetSymbolAddress((void**)&cmax,   g_cmax);
    cudaGetSymbolAddress((void**)&clse,   g_clse);

    float* out = (float*)d_out;

    const int TB = 256;
    int nb = (n + TB - 1) / TB;            // node blocks (also scan blocks)
    int eb = (E + TB - 1) / TB;            // edge blocks
    int gb = (n + 15) / 16;                // gemm blocks (16 nodes each)
    int wb  = (n * 32 + TB - 1) / TB;      // 1 warp per node
    int wb2 = (n * 64 + TB - 1) / TB;      // 2 warps per node

    // ---- CSR build + layer-1 GEMM interleaved (gemm1 independent of CSR) ----
    zero_deg_k<<<nb, TB>>>(deg, n);                                   // 1
    hist_k<<<eb, TB>>>(ei, deg, E);                                   // 2
    scan1_k<<<nb, TB>>>(deg, incl, bsum, n);                          // 3
    gemm_att_k<256, 64, 16, false><<<gb, 64>>>(x, W1, a1s, a1d,
                                               bufA, asrc, adst, n);  // 4 (profiled)
    scan2_k<<<1, TB>>>(bsum, nb);                                     // 5
    scan3_k<<<nb, TB>>>(incl, deg, bsum, rowptr, pos, n);             // 6
    scatter_k<<<eb, TB>>>(ei, pos, colx, E);                          // 7

    // ---- layer 1: 256 -> 64 ----
    alpha_k<<<wb, TB>>>(rowptr, colx, asrc, adst, exbuf, dinv, n);
    agg_gather_k<64, 1><<<wb, TB>>>(rowptr, colx, bufA, exbuf, dinv, b1, bufB, n);

    // ---- layer 2: 64 -> 256 (ReLU fused into input load) ----
    gemm_att_k<64, 256, 16, true><<<gb, 256>>>(bufB, W2, a2s, a2d, bufA, asrc, adst, n);
    alpha_k<<<wb, TB>>>(rowptr, colx, asrc, adst, exbuf, dinv, n);
    agg_gather_k<256, 2><<<wb2, TB>>>(rowptr, colx, bufA, exbuf, dinv, b2, bufB, n);

    // ---- layer 3: 256 -> 2 ----
    gemm3_k<<<wb, TB>>>(bufB, W3, a3s, a3d, h3, asrc, adst, n);
    gat_agg2_k<<<wb, TB>>>(rowptr, colx, h3, asrc, adst, b3, g3, n);

    // ---- classifier + log_softmax over nodes ----
    classifier_k<<<(n + TB - 1) / TB, TB>>>(g3, Wc, bc, logits, n);
    col_stats_k<<<NCLS, 256>>>(logits, cmax, clse, n);
    final_k<<<(n * NCLS + TB - 1) / TB, TB>>>(logits, cmax, clse, out, n * NCLS);
}